// round 15
// baseline (speedup 1.0000x reference)
#include <cuda_runtime.h>

#define BB 32
#define FF 35
#define SS 80
#define NC (2*FF+1)          // 71
#define NPAIR (BB*FF)        // 1120 chains, 1 chain per warp
#define WPB 8                // 8 warps per block -> 2 per SMSP
#define NB (NPAIR/WPB)       // 140 blocks
#define LN2F 0.69314718055994530942f

__device__ float g_loss[NPAIR];
__device__ unsigned g_count = 0;

__device__ __forceinline__ float frcp(float x) {
    float r; asm("rcp.approx.f32 %0, %1;" : "=f"(r) : "f"(x)); return r;
}

// mantissa-normalize into [1,2), accumulate exponent
#define EXTR(Z, ez) { int _bt = __float_as_int(Z); ez += (_bt >> 23) - 127; \
                      Z = __int_as_float((_bt & 0x7fffff) | 0x3f800000); }

__global__ __launch_bounds__(256, 1)
void ctc_fwd(const float* __restrict__ logits,
             const int*   __restrict__ targets,
             const int*   __restrict__ in_len,
             const int*   __restrict__ tgt_len,
             int T, float* __restrict__ out)
{
    __shared__ float2 sEE[WPB][32];    // per step: (e0', e1') blank-factored
    __shared__ float  sred[256];
    __shared__ int    sflag;

    const unsigned FM = 0xffffffffu;
    const int widb = threadIdx.x >> 5;
    const int lane = threadIdx.x & 31;
    const int c = blockIdx.x * WPB + widb;    // chain 0..1119

    const int b = c / FF, f = c - b * FF;
    const int tl = tgt_len[c];
    const int Lv = 2 * tl + 1;
    int Tin = in_len[b]; if (Tin > T) Tin = T;

    const int l0 = lane * 6;
    const int* tg = targets + (size_t)c * SS;

    // per-lane static constants; masks as integer AND-masks (ALU pipe in APPLY)
    const unsigned mb0 = (l0 + 0 < Lv) ? 0xffffffffu : 0u;
    const unsigned mb1 = (l0 + 1 < Lv) ? 0xffffffffu : 0u;
    const unsigned mb2 = (l0 + 2 < Lv) ? 0xffffffffu : 0u;
    const unsigned mb3 = (l0 + 3 < Lv) ? 0xffffffffu : 0u;
    const unsigned mb4 = (l0 + 4 < Lv) ? 0xffffffffu : 0u;
    const unsigned mb5 = (l0 + 5 < Lv) ? 0xffffffffu : 0u;
    bool  w1 = false, w3 = false, w5 = false;
    float sk1 = 0.f, sk3 = 0.f, sk5 = 0.f;
    {
        int l = l0 + 1;
        if (l < Lv) { int s = (l - 1) >> 1; int tv = tg[s];
            w1 = (tv != 0); sk1 = (l >= 3 && tg[s - 1] != tv) ? 1.f : 0.f; }
        l = l0 + 3;
        if (l < Lv) { int s = (l - 1) >> 1; int tv = tg[s];
            w3 = (tv != 0); sk3 = (l >= 3 && tg[s - 1] != tv) ? 1.f : 0.f; }
        l = l0 + 5;
        if (l < Lv) { int s = (l - 1) >> 1; int tv = tg[s];
            w5 = (tv != 0); sk5 = (l >= 3 && tg[s - 1] != tv) ? 1.f : 0.f; }
    }
    // lane 0: sk1 == 0 and lzm == 0 annihilate the garbage shfl_up value
    const float lzm = lane ? 1.f : 0.f;
    const float M1f = __uint_as_float(mb1) == 0.f ? 0.f : 1.f;   // for init only

    const float* pC = logits + (size_t)b * NC + f;   // chain's pos channel, t=0
    const int obl = 2 * FF - f;                      // pos -> blank offset
    const int TS = BB * NC;

    float A0 = 0.f, A1 = 0.f, A2 = 0.f, A3 = 0.f, A4 = 0.f, A5 = 0.f, a5p = 0.f;
    float Racc = 1.f;                 // running product of Z_t / e2_t (blank-factored Z)
    int ez = 0, E = 0;

    // ---- t = 0 init (full emissions; Z(0) folded into lane-0 Racc, no blank div) ----
    {
        float e0 = __expf(pC[0]), e1 = __expf(pC[FF]), e2 = __expf(pC[obl]);
        if (lane == 0) {
            A0 = e2;
            A1 = (w1 ? e1 : e0) * M1f;
            Racc = e0 + e1 + e2;
        }
    }

    // ---- prefetch first block (t = 1 + lane) ----
    float rp = 0.f, rn = 0.f, rb = 0.f;
    {
        int tt = 1 + lane;
        if (tt < Tin) {
            const float* q = pC + (size_t)tt * TS;
            rp = q[0]; rn = q[FF]; rb = q[obl];
        }
    }

// one CTC step. n5 first, its shuffle issued immediately; a5p consumers last.
#define STEP_EP(e0v, e1v) { \
    float t5v = w5 ? e1v : e0v; \
    float n5 = fmaf(sk5, A3, A5 + A4) * t5v; \
    float shv = __shfl_up_sync(FM, n5, 1); \
    float t1v = w1 ? e1v : e0v; \
    float t3v = w3 ? e1v : e0v; \
    float n3 = fmaf(sk3, A1, A3 + A2) * t3v; \
    float n2 = A2 + A1; \
    float n4 = A4 + A3; \
    float n1 = fmaf(sk1, a5p, A1 + A0) * t1v; \
    float n0 = fmaf(lzm, a5p, A0); \
    A0 = n0; A1 = n1; A2 = n2; A3 = n3; A4 = n4; A5 = n5; \
    a5p = shv; }

// exact power-of-2 rescale; junk states zeroed via integer AND masks (ALU pipe)
#define APPLY(sv) { \
    int ex = (__float_as_int(sv) >> 23) & 0xff; \
    ex = min(max(ex, 1), 253); \
    E += ex - 127; \
    float sc = __int_as_float((254 - ex) << 23); \
    A0 = __uint_as_float(__float_as_uint(A0 * sc) & mb0); \
    A1 = __uint_as_float(__float_as_uint(A1 * sc) & mb1); \
    A2 = __uint_as_float(__float_as_uint(A2 * sc) & mb2); \
    A3 = __uint_as_float(__float_as_uint(A3 * sc) & mb3); \
    A4 = __uint_as_float(__float_as_uint(A4 * sc) & mb4); \
    A5 = __uint_as_float(__float_as_uint(A5 * sc) & mb5); \
    a5p = __shfl_up_sync(FM, A5, 1); }

    for (int tb = 1; tb < Tin; tb += 32) {
        int ns = Tin - tb; if (ns > 32) ns = 32;

        // ---- stage blank-factored emissions; accumulate R = prod Z_t/e2_t ----
        float e0 = __expf(rp), e1 = __expf(rn), e2 = __expf(rb);
        float r2 = frcp(e2);
        __syncwarp();
        sEE[widb][lane] = make_float2(e0 * r2, e1 * r2);
        int tt = tb + lane;
        if (tt < Tin) {
            Racc *= (e0 + e1 + e2) * r2; EXTR(Racc, ez);
        }
        // prefetch next block
        int tn = tb + 32 + lane;
        if (tn < Tin) {
            const float* q = pC + (size_t)tn * TS;
            rp = q[0]; rn = q[FF]; rb = q[obl];
        }
        __syncwarp();

        if (ns == 32) {
            // fast path: LDS ring pipelined FOUR steps ahead (buries LDS
            // latency + L1 wavefront queueing); rescale every 16 steps,
            // butterfly spread over steps 11..15 / 27..31
            float sv = 0.f;
            float2 epr0 = sEE[widb][0];
            float2 epr1 = sEE[widb][1];
            float2 epr2 = sEE[widb][2];
            float2 epr3 = sEE[widb][3];
            #pragma unroll
            for (int i = 0; i < 32; i++) {
                float2 cur;
                switch (i & 3) {
                    case 0: cur = epr0; if (i < 28) epr0 = sEE[widb][i + 4]; break;
                    case 1: cur = epr1; if (i < 28) epr1 = sEE[widb][i + 4]; break;
                    case 2: cur = epr2; if (i < 28) epr2 = sEE[widb][i + 4]; break;
                    default: cur = epr3; if (i < 28) epr3 = sEE[widb][i + 4]; break;
                }
                STEP_EP(cur.x, cur.y);
                if (i == 10 || i == 26)
                    sv = ((A0 + A1) + (A2 + A3)) + (A4 + A5);
                if (i == 11 || i == 27) sv += __shfl_xor_sync(FM, sv, 1);
                if (i == 12 || i == 28) sv += __shfl_xor_sync(FM, sv, 2);
                if (i == 13 || i == 29) sv += __shfl_xor_sync(FM, sv, 4);
                if (i == 14 || i == 30) sv += __shfl_xor_sync(FM, sv, 8);
                if (i == 15 || i == 31) {
                    sv += __shfl_xor_sync(FM, sv, 16);
                    APPLY(sv);
                }
            }
        } else {
            // tail: single chain, loop just ends at Tin
            for (int i = 0; i < ns; i++) {
                float2 ep = sEE[widb][i];
                STEP_EP(ep.x, ep.y);
                if ((i & 7) == 7) {
                    float sv = ((A0 + A1) + (A2 + A3)) + (A4 + A5);
                    #pragma unroll
                    for (int o = 16; o; o >>= 1)
                        sv += __shfl_xor_sync(FM, sv, o);
                    APPLY(sv);
                }
            }
        }
    }

    // ---- final gather: alpha[2*tl] + alpha[2*tl-1] ----
    float last = 0.f, prv = 0.f;
    {
        int il = 2 * tl;
        #define GATH(j, R) { int l = l0 + j; \
            if (l == il) last = R; if (l == il - 1) prv = R; }
        GATH(0, A0) GATH(1, A1) GATH(2, A2)
        GATH(3, A3) GATH(4, A4) GATH(5, A5)
        #undef GATH
    }
    float fs = last + prv;
    float lz = __logf(Racc) + (float)ez * LN2F;
    #pragma unroll
    for (int o = 16; o; o >>= 1) {
        fs += __shfl_xor_sync(FM, fs, o);
        lz += __shfl_xor_sync(FM, lz, o);
    }
    if (lane == 0) {
        float lossv = 0.f;
        if (fs > 0.f) lossv = lz - (__logf(fs) + (float)E * LN2F);
        g_loss[c] = lossv / fmaxf((float)tl, 1.f);
    }

    // ---- fused grid reduction: last-arriving block sums g_loss ----
    __syncthreads();
    if (threadIdx.x == 0) {
        __threadfence();
        unsigned v = atomicAdd(&g_count, 1u);
        sflag = (v == gridDim.x - 1u) ? 1 : 0;
    }
    __syncthreads();
    if (sflag) {
        __threadfence();
        float acc = 0.f;
        for (int i = threadIdx.x; i < NPAIR; i += 256) acc += g_loss[i];
        sred[threadIdx.x] = acc;
        __syncthreads();
        #pragma unroll
        for (int o = 128; o; o >>= 1) {
            if (threadIdx.x < o) sred[threadIdx.x] += sred[threadIdx.x + o];
            __syncthreads();
        }
        if (threadIdx.x == 0) {
            out[0] = sred[0] * (1.0f / (float)BB);
            g_count = 0;
            __threadfence();
        }
    }
}

extern "C" void kernel_launch(void* const* d_in, const int* in_sizes, int n_in,
                              void* d_out, int out_size)
{
    const float* logits  = (const float*)d_in[0];
    const int*   targets = (const int*)d_in[1];
    const int*   in_len  = (const int*)d_in[2];
    const int*   tgt_len = (const int*)d_in[3];
    float* out = (float*)d_out;

    int T = in_sizes[0] / (BB * NC);   // 600

    // 140 blocks x 256 threads: 1120 warps, 1 chain each, 2 warps per SMSP
    ctc_fwd<<<NB, 256>>>(logits, targets, in_len, tgt_len, T, out);
}